// round 1
// baseline (speedup 1.0000x reference)
#include <cuda_runtime.h>
#include <cstdint>

// ---------------------------------------------------------------------------
// LoRA multi-task MLP:  3 x ( C = H*W + b + SCALING * (H*D_t)*U_t ), ReLU on
// layers 0,1.  T=8 tasks, B=1024 rows/task -> M=8192.  RANK=8, SCALING=2.
// Round 0: fp32 SIMT tiled GEMM with fused LoRA epilogue (correct baseline).
// ---------------------------------------------------------------------------

#define T_TASKS 8
#define RNK 8
#define SCALING 2.0f

#define M_ROWS (8 * 1024)      // T*B
#define H1 2048
#define H2 2048
#define H3 1024
#define D0 1024

// Scratch (device globals: no allocation allowed in kernel_launch)
__device__ float g_h1[M_ROWS * H1];   // 64 MB
__device__ float g_h2[M_ROWS * H2];   // 64 MB
__device__ float g_p [M_ROWS * RNK];  // 256 KB (reused each layer)

// ---------------------------------------------------------------------------
// P[m, r] = sum_k H[m,k] * D[k, r, t]   with t = m >> 10
// D layout: [K, RNK, T] row-major  ->  D[k*RNK*T + r*T + t]
// One warp per row m.
// ---------------------------------------------------------------------------
__global__ __launch_bounds__(256)
void lora_down_kernel(const float* __restrict__ H,
                      const float* __restrict__ D,
                      float* __restrict__ P, int K)
{
    int warp = (blockIdx.x * blockDim.x + threadIdx.x) >> 5;
    int lane = threadIdx.x & 31;
    if (warp >= M_ROWS) return;
    int t = warp >> 10;
    const float* h = H + (size_t)warp * K;

    float acc[RNK];
#pragma unroll
    for (int r = 0; r < RNK; ++r) acc[r] = 0.f;

    for (int k = lane; k < K; k += 32) {
        float hv = h[k];
        const float* dp = D + (size_t)k * (RNK * T_TASKS) + t;
#pragma unroll
        for (int r = 0; r < RNK; ++r)
            acc[r] += hv * dp[r * T_TASKS];
    }
#pragma unroll
    for (int r = 0; r < RNK; ++r) {
        float v = acc[r];
#pragma unroll
        for (int o = 16; o > 0; o >>= 1)
            v += __shfl_down_sync(0xffffffffu, v, o);
        if (lane == 0) P[(size_t)warp * RNK + r] = v;
    }
}

// ---------------------------------------------------------------------------
// C[m,n] = relu?( A[m,:]*W[:,n] + bias[n] + SCALING * sum_r P[m,r]*U[r,n,t] )
// Tile: BM=128, BN=64, BK=16; 256 threads; 8x4 microtile per thread.
// U layout: [RNK, N, T] row-major -> U[r*N*T + n*T + t]
// A block never straddles a task boundary (1024 % 128 == 0).
// ---------------------------------------------------------------------------
#define BM 128
#define BN 64
#define BK 16

__global__ __launch_bounds__(256)
void gemm_lora_kernel(const float* __restrict__ A,    // [M, K]
                      const float* __restrict__ W,    // [K, N]
                      const float* __restrict__ bias, // [N]
                      const float* __restrict__ P,    // [M, RNK]
                      const float* __restrict__ U,    // [RNK, N, T]
                      float* __restrict__ C,          // [M, N]
                      int K, int N, int relu)
{
    __shared__ float As[BK][BM + 4];
    __shared__ float Bs[BK][BN];
    __shared__ float Ps[BM][RNK];
    __shared__ float Us[RNK][BN];

    const int tid = threadIdx.x;          // 0..255
    const int tx  = tid & 15;             // 16 col groups of 4
    const int ty  = tid >> 4;             // 16 row groups of 8
    const int mBase = blockIdx.y * BM;
    const int nBase = blockIdx.x * BN;
    const int t = mBase >> 10;            // task id (constant per block)

    float acc[8][4];
#pragma unroll
    for (int i = 0; i < 8; ++i)
#pragma unroll
        for (int j = 0; j < 4; ++j) acc[i][j] = 0.f;

    const float* Ab = A + (size_t)mBase * K;

    for (int k0 = 0; k0 < K; k0 += BK) {
        // --- load A tile (128x16) as 512 float4s: 2 per thread ---
#pragma unroll
        for (int i = 0; i < 2; ++i) {
            int f4  = tid + i * 256;
            int row = f4 >> 2;
            int kq  = (f4 & 3) << 2;
            float4 v = *reinterpret_cast<const float4*>(
                Ab + (size_t)row * K + k0 + kq);
            As[kq + 0][row] = v.x;
            As[kq + 1][row] = v.y;
            As[kq + 2][row] = v.z;
            As[kq + 3][row] = v.w;
        }
        // --- load B tile (16x64): 1 float4 per thread ---
        {
            int kk = tid >> 4;
            int nq = (tid & 15) << 2;
            float4 v = *reinterpret_cast<const float4*>(
                W + (size_t)(k0 + kk) * N + nBase + nq);
            *reinterpret_cast<float4*>(&Bs[kk][nq]) = v;
        }
        __syncthreads();

#pragma unroll
        for (int kk = 0; kk < BK; ++kk) {
            float ra[8], rb[4];
#pragma unroll
            for (int i = 0; i < 8; ++i) ra[i] = As[kk][ty * 8 + i];
#pragma unroll
            for (int j = 0; j < 4; ++j) rb[j] = Bs[kk][tx * 4 + j];
#pragma unroll
            for (int i = 0; i < 8; ++i)
#pragma unroll
                for (int j = 0; j < 4; ++j)
                    acc[i][j] += ra[i] * rb[j];
        }
        __syncthreads();
    }

    // --- epilogue: load P tile (128x8) and U tile (8x64) into smem ---
    {
        int row  = tid >> 1;
        int half = (tid & 1) << 2;
        float4 v = *reinterpret_cast<const float4*>(
            P + (size_t)(mBase + row) * RNK + half);
        *reinterpret_cast<float4*>(&Ps[row][half]) = v;
    }
#pragma unroll
    for (int i = 0; i < 2; ++i) {
        int id = tid + i * 256;
        int rr = id >> 6;
        int f  = id & 63;
        Us[rr][f] = U[((size_t)rr * N + nBase + f) * T_TASKS + t];
    }
    __syncthreads();

#pragma unroll
    for (int i = 0; i < 8; ++i) {
        const int lrow = ty * 8 + i;
        const int gm   = mBase + lrow;
        float pr[RNK];
#pragma unroll
        for (int r = 0; r < RNK; ++r) pr[r] = Ps[lrow][r];

        float o[4];
#pragma unroll
        for (int j = 0; j < 4; ++j) {
            int gn = nBase + tx * 4 + j;
            float l = 0.f;
#pragma unroll
            for (int r = 0; r < RNK; ++r)
                l += pr[r] * Us[r][tx * 4 + j];
            float v = acc[i][j] + bias[gn] + SCALING * l;
            if (relu) v = fmaxf(v, 0.f);
            o[j] = v;
        }
        float4 ov = make_float4(o[0], o[1], o[2], o[3]);
        *reinterpret_cast<float4*>(C + (size_t)gm * N + nBase + tx * 4) = ov;
    }
}

// ---------------------------------------------------------------------------
// Host launcher.  Inputs (fp32): x,k0,b0,d0,u0,k1,b1,d1,u1,k2,b2,d2,u2
// ---------------------------------------------------------------------------
extern "C" void kernel_launch(void* const* d_in, const int* in_sizes, int n_in,
                              void* d_out, int out_size)
{
    const float* x  = (const float*)d_in[0];
    const float* k0 = (const float*)d_in[1];
    const float* b0 = (const float*)d_in[2];
    const float* d0 = (const float*)d_in[3];
    const float* u0 = (const float*)d_in[4];
    const float* k1 = (const float*)d_in[5];
    const float* b1 = (const float*)d_in[6];
    const float* d1 = (const float*)d_in[7];
    const float* u1 = (const float*)d_in[8];
    const float* k2 = (const float*)d_in[9];
    const float* b2 = (const float*)d_in[10];
    const float* d2 = (const float*)d_in[11];
    const float* u2 = (const float*)d_in[12];
    float* out = (float*)d_out;

    float *h1, *h2, *p;
    cudaGetSymbolAddress((void**)&h1, g_h1);
    cudaGetSymbolAddress((void**)&h2, g_h2);
    cudaGetSymbolAddress((void**)&p,  g_p);

    const int downBlocks = M_ROWS / 8;   // 8 warps per 256-thread block

    // ---- layer 0: x[8192,1024] -> h1[8192,2048], ReLU ----
    lora_down_kernel<<<downBlocks, 256>>>(x, d0, p, D0);
    {
        dim3 grid(H1 / BN, M_ROWS / BM);
        gemm_lora_kernel<<<grid, 256>>>(x, k0, b0, p, u0, h1, D0, H1, 1);
    }

    // ---- layer 1: h1[8192,2048] -> h2[8192,2048], ReLU ----
    lora_down_kernel<<<downBlocks, 256>>>(h1, d1, p, H1);
    {
        dim3 grid(H2 / BN, M_ROWS / BM);
        gemm_lora_kernel<<<grid, 256>>>(h1, k1, b1, p, u1, h2, H1, H2, 1);
    }

    // ---- layer 2: h2[8192,2048] -> out[8192,1024], no ReLU ----
    lora_down_kernel<<<downBlocks, 256>>>(h2, d2, p, H2);
    {
        dim3 grid(H3 / BN, M_ROWS / BM);
        gemm_lora_kernel<<<grid, 256>>>(h2, k2, b2, p, u2, out, H2, H3, 0);
    }
}

// round 3
// speedup vs baseline: 1.8688x; 1.8688x over previous
#include <cuda_runtime.h>
#include <cuda_bf16.h>
#include <cstdint>

// ---------------------------------------------------------------------------
// LoRA multi-task MLP via mma.sync bf16 (portable to plain sm_100 target).
// fp32 operands split hi/lo into bf16; GEMM computes
//   Ahi*Whi + Ahi*Wlo + Alo*Whi  via K-concatenation (K' = 3K), fp32 accum.
// ---------------------------------------------------------------------------

#define T_TASKS 8
#define RNK 8
#define M_ROWS 8192
#define H1 2048
#define H2 2048
#define H3 1024
#define D0 1024

#define BM 128
#define BN 128
#define BK 64                       // bf16 elements per chunk (128 B rows)
#define STAGES 4
#define STAGE_BYTES (BM*128 + BN*128)   // 16KB A + 16KB B = 32KB
#define SMEM_BYTES  (STAGES * STAGE_BYTES)

// ---- scratch (device globals; no allocation allowed) ----------------------
__device__ float g_h1[M_ROWS * H1];
__device__ float g_h2[M_ROWS * H2];
__device__ float g_p [M_ROWS * RNK];
__device__ __nv_bfloat16 g_Asplit[(size_t)M_ROWS * 3 * 2048];
__device__ __nv_bfloat16 g_Bsplit[(size_t)2048  * 3 * 2048];

// ---------------------------------------------------------------------------
__device__ __forceinline__ uint32_t smem_u32(const void* p) {
    uint32_t a;
    asm("{ .reg .u64 t; cvta.to.shared.u64 t, %1; cvt.u32.u64 %0, t; }"
        : "=r"(a) : "l"(p));
    return a;
}

#define CP_ASYNC16(smem, gptr) \
    asm volatile("cp.async.cg.shared.global [%0], [%1], 16;" \
                 :: "r"(smem), "l"(gptr) : "memory")
#define CP_ASYNC_COMMIT() asm volatile("cp.async.commit_group;" ::: "memory")
#define CP_ASYNC_WAIT(n)  asm volatile("cp.async.wait_group %0;" :: "n"(n) : "memory")

#define LDMATRIX_X4(r0,r1,r2,r3,addr) \
    asm volatile("ldmatrix.sync.aligned.m8n8.x4.shared.b16 {%0,%1,%2,%3}, [%4];" \
        : "=r"(r0),"=r"(r1),"=r"(r2),"=r"(r3) : "r"(addr))
#define LDMATRIX_X2(r0,r1,addr) \
    asm volatile("ldmatrix.sync.aligned.m8n8.x2.shared.b16 {%0,%1}, [%2];" \
        : "=r"(r0),"=r"(r1) : "r"(addr))

__device__ __forceinline__ void mma_bf16(float* c, const uint32_t* a,
                                         const uint32_t* b) {
    asm volatile(
        "mma.sync.aligned.m16n8k16.row.col.f32.bf16.bf16.f32 "
        "{%0,%1,%2,%3}, {%4,%5,%6,%7}, {%8,%9}, {%0,%1,%2,%3};"
        : "+f"(c[0]), "+f"(c[1]), "+f"(c[2]), "+f"(c[3])
        : "r"(a[0]), "r"(a[1]), "r"(a[2]), "r"(a[3]), "r"(b[0]), "r"(b[1]));
}

// ---------------------------------------------------------------------------
// P[m,r] = sum_k H[m,k] * D[k,r,t],  t = m >> 10.  One warp per row.
// ---------------------------------------------------------------------------
__global__ __launch_bounds__(256)
void lora_down_kernel(const float* __restrict__ H, const float* __restrict__ D,
                      float* __restrict__ P, int K)
{
    int warp = (blockIdx.x * blockDim.x + threadIdx.x) >> 5;
    int lane = threadIdx.x & 31;
    if (warp >= M_ROWS) return;
    int t = warp >> 10;
    const float* h = H + (size_t)warp * K;
    float acc[RNK];
#pragma unroll
    for (int r = 0; r < RNK; ++r) acc[r] = 0.f;
    for (int k = lane; k < K; k += 32) {
        float hv = h[k];
        const float* dp = D + (size_t)k * (RNK * T_TASKS) + t;
#pragma unroll
        for (int r = 0; r < RNK; ++r) acc[r] += hv * dp[r * T_TASKS];
    }
#pragma unroll
    for (int r = 0; r < RNK; ++r) {
        float v = acc[r];
#pragma unroll
        for (int o = 16; o > 0; o >>= 1) v += __shfl_down_sync(0xffffffffu, v, o);
        if (lane == 0) P[(size_t)warp * RNK + r] = v;
    }
}

// ---------------------------------------------------------------------------
// A[M,K] fp32 -> A'[M,3K] bf16 = [hi | hi | lo]
// ---------------------------------------------------------------------------
__global__ __launch_bounds__(256)
void convertA_kernel(const float* __restrict__ A, __nv_bfloat16* __restrict__ Ap,
                     int K)
{
    size_t idx = (size_t)blockIdx.x * blockDim.x + threadIdx.x;
    size_t total = (size_t)M_ROWS * K / 4;
    if (idx >= total) return;
    int Kq = K >> 2;
    int m  = (int)(idx / Kq);
    int kq = (int)(idx - (size_t)m * Kq) << 2;
    float4 v = *reinterpret_cast<const float4*>(A + (size_t)m * K + kq);

    union { __nv_bfloat16 b[4]; uint2 u; } hp, lp;
    float vv[4] = {v.x, v.y, v.z, v.w};
#pragma unroll
    for (int i = 0; i < 4; ++i) {
        __nv_bfloat16 h = __float2bfloat16(vv[i]);
        hp.b[i] = h;
        lp.b[i] = __float2bfloat16(vv[i] - __bfloat162float(h));
    }
    size_t base = (size_t)m * 3 * K + kq;
    *reinterpret_cast<uint2*>(Ap + base)         = hp.u;
    *reinterpret_cast<uint2*>(Ap + base + K)     = hp.u;
    *reinterpret_cast<uint2*>(Ap + base + 2 * K) = lp.u;
}

// ---------------------------------------------------------------------------
// W[K,N] fp32 -> B'[N,3K] bf16 = [hi^T | lo^T | hi^T]
// ---------------------------------------------------------------------------
__global__ __launch_bounds__(256)
void convertW_kernel(const float* __restrict__ W, __nv_bfloat16* __restrict__ Bp,
                     int K, int N)
{
    __shared__ float t[32][33];
    int n0 = blockIdx.x * 32, k0 = blockIdx.y * 32;
    int tx = threadIdx.x & 31, ty = threadIdx.x >> 5;   // 32 x 8
#pragma unroll
    for (int i = 0; i < 4; ++i)
        t[ty + 8 * i][tx] = W[(size_t)(k0 + ty + 8 * i) * N + n0 + tx];
    __syncthreads();
#pragma unroll
    for (int i = 0; i < 4; ++i) {
        int nn = ty + 8 * i;
        float v = t[tx][nn];
        __nv_bfloat16 h = __float2bfloat16(v);
        __nv_bfloat16 l = __float2bfloat16(v - __bfloat162float(h));
        size_t rb = (size_t)(n0 + nn) * 3 * K + k0 + tx;
        Bp[rb]         = h;
        Bp[rb + K]     = l;
        Bp[rb + 2 * K] = h;
    }
}

// ---------------------------------------------------------------------------
// Pipelined bf16 mma.sync GEMM with fused LoRA epilogue.
//   C[m,n] = relu?( A'[m,:]*B'[n,:] + bias[n] + 2 * sum_r P[m,r]*U[r,n,t] )
// A'[M,3K], B'[N,3K] bf16 K-major. Smem tiles SW128-swizzled for ldmatrix.
// ---------------------------------------------------------------------------
__global__ __launch_bounds__(256, 1)
void gemm_mma_kernel(const __nv_bfloat16* __restrict__ Ap,
                     const __nv_bfloat16* __restrict__ Bp,
                     const float* __restrict__ bias,
                     const float* __restrict__ P,
                     const float* __restrict__ U,
                     float* __restrict__ C,
                     int K3, int N, int nChunks, int relu)
{
    extern __shared__ char smem[];
    const uint32_t sbase = smem_u32(smem);
    const int tid  = threadIdx.x;
    const int wid  = tid >> 5;
    const int lane = tid & 31;
    const int mBase = blockIdx.y * BM;
    const int nBase = blockIdx.x * BN;
    const int task  = mBase >> 10;

    const int warp_m = (wid >> 2) * 64;   // 0 / 64
    const int warp_n = (wid & 3) * 32;    // 0 / 32 / 64 / 96

    // ---- per-thread producer addressing (4 A chunks + 4 B chunks) ----------
    const __nv_bfloat16* gA[4];
    const __nv_bfloat16* gB[4];
    uint32_t sA[4], sB[4];
#pragma unroll
    for (int i = 0; i < 4; ++i) {
        int g = tid + (i << 8);           // 0..1023 = 16B granule id
        int r = g >> 3, q = g & 7;        // row 0..127, 16B col 0..7
        uint32_t off = (uint32_t)(r << 7) + (q << 4);
        uint32_t sw  = off ^ ((uint32_t)(r & 7) << 4);
        sA[i] = sw;
        sB[i] = sw;
        gA[i] = Ap + (size_t)(mBase + r) * K3 + (q << 3);
        gB[i] = Bp + (size_t)(nBase + r) * K3 + (q << 3);
    }

    float acc[4][4][4];
#pragma unroll
    for (int mi = 0; mi < 4; ++mi)
#pragma unroll
        for (int ni = 0; ni < 4; ++ni)
#pragma unroll
            for (int j = 0; j < 4; ++j) acc[mi][ni][j] = 0.f;

    // ---- prologue: fill STAGES-1 stages -----------------------------------
#pragma unroll
    for (int c = 0; c < STAGES - 1; ++c) {
        const uint32_t stA = sbase + c * STAGE_BYTES;
        const uint32_t stB = stA + BM * 128;
        const int kc = c * BK;
#pragma unroll
        for (int i = 0; i < 4; ++i) CP_ASYNC16(stA + sA[i], gA[i] + kc);
#pragma unroll
        for (int i = 0; i < 4; ++i) CP_ASYNC16(stB + sB[i], gB[i] + kc);
        CP_ASYNC_COMMIT();
    }

    // ---- precomputed ldmatrix row terms ------------------------------------
    // A: row = warp_m + mi*16 + (lane&15); col16 = (lane>>4) (0/1 -> +16B)
    // B: row = warp_n + ni*8  + (lane&7);  col16 = (lane>>3)&1
    uint32_t aRow[4], aXm[4], bRow[4], bXm[4];
    const uint32_t aCol = (uint32_t)(lane >> 4) << 4;
    const uint32_t bCol = (uint32_t)((lane >> 3) & 1) << 4;
#pragma unroll
    for (int mi = 0; mi < 4; ++mi) {
        int r = warp_m + mi * 16 + (lane & 15);
        aRow[mi] = (uint32_t)r << 7;
        aXm[mi]  = (uint32_t)(r & 7) << 4;
    }
#pragma unroll
    for (int ni = 0; ni < 4; ++ni) {
        int r = warp_n + ni * 8 + (lane & 7);
        bRow[ni] = (uint32_t)r << 7;
        bXm[ni]  = (uint32_t)(r & 7) << 4;
    }

    // ---- mainloop ----------------------------------------------------------
    for (int c = 0; c < nChunks; ++c) {
        CP_ASYNC_WAIT(STAGES - 2);
        __syncthreads();

        const int s = c & (STAGES - 1);
        const uint32_t stA = sbase + s * STAGE_BYTES;
        const uint32_t stB = stA + BM * 128;

#pragma unroll
        for (int kk = 0; kk < 4; ++kk) {
            const uint32_t kb = (uint32_t)kk << 5;   // +32 B per k16
            uint32_t a[4][4], b[4][2];
#pragma unroll
            for (int mi = 0; mi < 4; ++mi) {
                uint32_t addr = stA + aRow[mi] + (((kb + aCol)) ^ aXm[mi]);
                LDMATRIX_X4(a[mi][0], a[mi][1], a[mi][2], a[mi][3], addr);
            }
#pragma unroll
            for (int ni = 0; ni < 4; ++ni) {
                uint32_t addr = stB + bRow[ni] + (((kb + bCol)) ^ bXm[ni]);
                LDMATRIX_X2(b[ni][0], b[ni][1], addr);
            }
#pragma unroll
            for (int mi = 0; mi < 4; ++mi)
#pragma unroll
                for (int ni = 0; ni < 4; ++ni)
                    mma_bf16(acc[mi][ni], a[mi], b[ni]);
        }

        const int cn = c + STAGES - 1;
        if (cn < nChunks) {
            const int sn = cn & (STAGES - 1);
            const uint32_t nA = sbase + sn * STAGE_BYTES;
            const uint32_t nB = nA + BM * 128;
            const int kc = cn * BK;
#pragma unroll
            for (int i = 0; i < 4; ++i) CP_ASYNC16(nA + sA[i], gA[i] + kc);
#pragma unroll
            for (int i = 0; i < 4; ++i) CP_ASYNC16(nB + sB[i], gB[i] + kc);
        }
        CP_ASYNC_COMMIT();
    }

    // ---- epilogue: stage bias/U/P in smem, fuse LoRA + ReLU ----------------
    CP_ASYNC_WAIT(0);
    __syncthreads();

    float* bias_s = reinterpret_cast<float*>(smem);            // [128]
    float* Us     = reinterpret_cast<float*>(smem + 1024);     // [8][128]
    float* Ps     = reinterpret_cast<float*>(smem + 1024 + 4096); // [128][8]

    if (tid < BN) bias_s[tid] = bias[nBase + tid];
#pragma unroll
    for (int i = 0; i < 4; ++i) {
        int idx = tid + (i << 8);
        int r = idx >> 7, n = idx & 127;
        Us[idx] = U[((size_t)r * N + nBase + n) * T_TASKS + task];
    }
    {
        int row = tid >> 1, half = (tid & 1) << 2;
        float4 v = *reinterpret_cast<const float4*>(
            P + (size_t)(mBase + row) * RNK + half);
        *reinterpret_cast<float4*>(&Ps[row * RNK + half]) = v;
    }
    __syncthreads();

#pragma unroll
    for (int mi = 0; mi < 4; ++mi) {
#pragma unroll
        for (int half = 0; half < 2; ++half) {
            const int rloc = warp_m + mi * 16 + (lane >> 2) + half * 8;
            float pr[RNK];
            {
                float4 p0 = *reinterpret_cast<const float4*>(&Ps[rloc * RNK]);
                float4 p1 = *reinterpret_cast<const float4*>(&Ps[rloc * RNK + 4]);
                pr[0]=p0.x; pr[1]=p0.y; pr[2]=p0.z; pr[3]=p0.w;
                pr[4]=p1.x; pr[5]=p1.y; pr[6]=p1.z; pr[7]=p1.w;
            }
            float* crow = C + (size_t)(mBase + rloc) * N + nBase;
#pragma unroll
            for (int ni = 0; ni < 4; ++ni) {
                const int nloc = warp_n + ni * 8 + ((lane & 3) << 1);
                float l0 = 0.f, l1 = 0.f;
#pragma unroll
                for (int q = 0; q < RNK; ++q) {
                    l0 += pr[q] * Us[(q << 7) + nloc];
                    l1 += pr[q] * Us[(q << 7) + nloc + 1];
                }
                float v0 = acc[mi][ni][half * 2 + 0] + bias_s[nloc]     + 2.f * l0;
                float v1 = acc[mi][ni][half * 2 + 1] + bias_s[nloc + 1] + 2.f * l1;
                if (relu) { v0 = fmaxf(v0, 0.f); v1 = fmaxf(v1, 0.f); }
                *reinterpret_cast<float2*>(crow + nloc) = make_float2(v0, v1);
            }
        }
    }
}

// ---------------------------------------------------------------------------
// Host launcher
// ---------------------------------------------------------------------------
static void run_layer(const float* Ain, const float* W, const float* b,
                      const float* D, const float* U, float* Cout,
                      __nv_bfloat16* aS, __nv_bfloat16* bS, float* p,
                      int K, int N, int relu)
{
    convertW_kernel<<<dim3(N / 32, K / 32), 256>>>(W, bS, K, N);
    lora_down_kernel<<<M_ROWS / 8, 256>>>(Ain, D, p, K);
    {
        size_t tot = (size_t)M_ROWS * K / 4;
        convertA_kernel<<<(unsigned)((tot + 255) / 256), 256>>>(Ain, aS, K);
    }
    cudaFuncSetAttribute(gemm_mma_kernel,
                         cudaFuncAttributeMaxDynamicSharedMemorySize, SMEM_BYTES);
    dim3 grid(N / BN, M_ROWS / BM);
    gemm_mma_kernel<<<grid, 256, SMEM_BYTES>>>(
        aS, bS, b, p, U, Cout, 3 * K, N, 3 * K / BK, relu);
}

extern "C" void kernel_launch(void* const* d_in, const int* in_sizes, int n_in,
                              void* d_out, int out_size)
{
    const float* x  = (const float*)d_in[0];
    const float* k0 = (const float*)d_in[1];
    const float* b0 = (const float*)d_in[2];
    const float* d0 = (const float*)d_in[3];
    const float* u0 = (const float*)d_in[4];
    const float* k1 = (const float*)d_in[5];
    const float* b1 = (const float*)d_in[6];
    const float* d1 = (const float*)d_in[7];
    const float* u1 = (const float*)d_in[8];
    const float* k2 = (const float*)d_in[9];
    const float* b2 = (const float*)d_in[10];
    const float* d2 = (const float*)d_in[11];
    const float* u2 = (const float*)d_in[12];
    float* out = (float*)d_out;

    float *h1, *h2, *p;
    __nv_bfloat16 *aS, *bS;
    cudaGetSymbolAddress((void**)&h1, g_h1);
    cudaGetSymbolAddress((void**)&h2, g_h2);
    cudaGetSymbolAddress((void**)&p,  g_p);
    cudaGetSymbolAddress((void**)&aS, g_Asplit);
    cudaGetSymbolAddress((void**)&bS, g_Bsplit);

    run_layer(x,  k0, b0, d0, u0, h1,  aS, bS, p, D0, H1, 1);
    run_layer(h1, k1, b1, d1, u1, h2,  aS, bS, p, H1, H2, 1);
    run_layer(h2, k2, b2, d2, u2, out, aS, bS, p, H2, H3, 0);
}

// round 4
// speedup vs baseline: 3.2816x; 1.7560x over previous
#include <cuda_runtime.h>
#include <cuda_bf16.h>
#include <cstdint>

// ---------------------------------------------------------------------------
// LoRA multi-task MLP via mma.sync bf16 (plain sm_100 target).
// fp32 operands split hi/lo bf16, stored as [hi|lo] (2K wide). GEMM computes
//   Ahi*Whi + Ahi*Wlo + Alo*Whi  (3 K-passes mapped onto the 2K layout).
// Activations stay bf16 [hi|lo] end-to-end: the GEMM epilogue emits the split
// directly (fused with bias + 2*P*U^t + ReLU); only the last layer emits fp32.
// ---------------------------------------------------------------------------

#define T_TASKS 8
#define RNK 8
#define M_ROWS 8192

#define BM 128
#define BN 128
#define BK 64                       // bf16 elements per chunk (128 B rows)
#define STAGES 4
#define STAGE_BYTES (BM*128 + BN*128)   // 16KB A + 16KB B = 32KB
#define SMEM_BYTES  (STAGES * STAGE_BYTES)

// ---- scratch (device globals; no allocation allowed) ----------------------
__device__ __nv_bfloat16 g_A0[(size_t)M_ROWS * 4096];   // [hi|lo], 64 MB
__device__ __nv_bfloat16 g_A1[(size_t)M_ROWS * 4096];   // [hi|lo], 64 MB
__device__ __nv_bfloat16 g_B [(size_t)2048   * 4096];   // [hi|lo], 16 MB
__device__ float g_p[M_ROWS * RNK];

// ---------------------------------------------------------------------------
__device__ __forceinline__ uint32_t smem_u32(const void* p) {
    uint32_t a;
    asm("{ .reg .u64 t; cvta.to.shared.u64 t, %1; cvt.u32.u64 %0, t; }"
        : "=r"(a) : "l"(p));
    return a;
}

#define CP_ASYNC16(smem, gptr) \
    asm volatile("cp.async.cg.shared.global [%0], [%1], 16;" \
                 :: "r"(smem), "l"(gptr) : "memory")
#define CP_ASYNC_COMMIT() asm volatile("cp.async.commit_group;" ::: "memory")
#define CP_ASYNC_WAIT(n)  asm volatile("cp.async.wait_group %0;" :: "n"(n) : "memory")

#define LDMATRIX_X4(r0,r1,r2,r3,addr) \
    asm volatile("ldmatrix.sync.aligned.m8n8.x4.shared.b16 {%0,%1,%2,%3}, [%4];" \
        : "=r"(r0),"=r"(r1),"=r"(r2),"=r"(r3) : "r"(addr))
#define LDMATRIX_X2(r0,r1,addr) \
    asm volatile("ldmatrix.sync.aligned.m8n8.x2.shared.b16 {%0,%1}, [%2];" \
        : "=r"(r0),"=r"(r1) : "r"(addr))

__device__ __forceinline__ void mma_bf16(float* c, const uint32_t* a,
                                         const uint32_t* b) {
    asm volatile(
        "mma.sync.aligned.m16n8k16.row.col.f32.bf16.bf16.f32 "
        "{%0,%1,%2,%3}, {%4,%5,%6,%7}, {%8,%9}, {%0,%1,%2,%3};"
        : "+f"(c[0]), "+f"(c[1]), "+f"(c[2]), "+f"(c[3])
        : "r"(a[0]), "r"(a[1]), "r"(a[2]), "r"(a[3]), "r"(b[0]), "r"(b[1]));
}

// ---------------------------------------------------------------------------
// P[m,r] = sum_k H[m,k] * D[k,r,t],  H given as bf16 [hi|lo] rows (stride 2K).
// Block = 8 warps = 8 rows (never straddles a task).  D chunk staged in smem.
// ---------------------------------------------------------------------------
#define LD_CHUNK 512
__global__ __launch_bounds__(256)
void lora_down_kernel(const __nv_bfloat16* __restrict__ A,
                      const float* __restrict__ D,
                      float* __restrict__ P, int K)
{
    __shared__ float Ds[RNK][LD_CHUNK + 1];
    const int tid  = threadIdx.x;
    const int wid  = tid >> 5;
    const int lane = tid & 31;
    const int row  = blockIdx.x * 8 + wid;
    const int t    = (blockIdx.x * 8) >> 10;
    const __nv_bfloat16* rowp = A + (size_t)row * (2 * K);

    float acc[RNK];
#pragma unroll
    for (int r = 0; r < RNK; ++r) acc[r] = 0.f;

    for (int k0 = 0; k0 < K; k0 += LD_CHUNK) {
        __syncthreads();
        for (int idx = tid; idx < LD_CHUNK * RNK; idx += 256) {
            int k = idx >> 3, r = idx & 7;
            Ds[r][k] = D[(size_t)(k0 + k) * (RNK * T_TASKS) + r * T_TASKS + t];
        }
        __syncthreads();
        for (int kk = lane; kk < LD_CHUNK; kk += 32) {
            float h = __bfloat162float(rowp[k0 + kk]) +
                      __bfloat162float(rowp[K + k0 + kk]);
#pragma unroll
            for (int r = 0; r < RNK; ++r) acc[r] += h * Ds[r][kk];
        }
    }
#pragma unroll
    for (int r = 0; r < RNK; ++r) {
        float v = acc[r];
#pragma unroll
        for (int o = 16; o > 0; o >>= 1) v += __shfl_down_sync(0xffffffffu, v, o);
        if (lane == 0) P[(size_t)row * RNK + r] = v;
    }
}

// ---------------------------------------------------------------------------
// x[M,K] fp32 -> A'[M,2K] bf16 = [hi | lo]   (layer-0 input only)
// ---------------------------------------------------------------------------
__global__ __launch_bounds__(256)
void convertA_kernel(const float* __restrict__ A, __nv_bfloat16* __restrict__ Ap,
                     int K)
{
    size_t idx = (size_t)blockIdx.x * blockDim.x + threadIdx.x;
    size_t total = (size_t)M_ROWS * K / 4;
    if (idx >= total) return;
    int Kq = K >> 2;
    int m  = (int)(idx / Kq);
    int kq = (int)(idx - (size_t)m * Kq) << 2;
    float4 v = *reinterpret_cast<const float4*>(A + (size_t)m * K + kq);

    union { __nv_bfloat16 b[4]; uint2 u; } hp, lp;
    float vv[4] = {v.x, v.y, v.z, v.w};
#pragma unroll
    for (int i = 0; i < 4; ++i) {
        __nv_bfloat16 h = __float2bfloat16(vv[i]);
        hp.b[i] = h;
        lp.b[i] = __float2bfloat16(vv[i] - __bfloat162float(h));
    }
    size_t base = (size_t)m * 2 * K + kq;
    *reinterpret_cast<uint2*>(Ap + base)     = hp.u;
    *reinterpret_cast<uint2*>(Ap + base + K) = lp.u;
}

// ---------------------------------------------------------------------------
// W[K,N] fp32 -> B'[N,2K] bf16 = [hi^T | lo^T]
// ---------------------------------------------------------------------------
__global__ __launch_bounds__(256)
void convertW_kernel(const float* __restrict__ W, __nv_bfloat16* __restrict__ Bp,
                     int K, int N)
{
    __shared__ float t[32][33];
    int n0 = blockIdx.x * 32, k0 = blockIdx.y * 32;
    int tx = threadIdx.x & 31, ty = threadIdx.x >> 5;   // 32 x 8
#pragma unroll
    for (int i = 0; i < 4; ++i)
        t[ty + 8 * i][tx] = W[(size_t)(k0 + ty + 8 * i) * N + n0 + tx];
    __syncthreads();
#pragma unroll
    for (int i = 0; i < 4; ++i) {
        int nn = ty + 8 * i;
        float v = t[tx][nn];
        __nv_bfloat16 h = __float2bfloat16(v);
        __nv_bfloat16 l = __float2bfloat16(v - __bfloat162float(h));
        size_t rb = (size_t)(n0 + nn) * 2 * K + k0 + tx;
        Bp[rb]     = h;
        Bp[rb + K] = l;
    }
}

// ---------------------------------------------------------------------------
// Pipelined bf16 mma.sync GEMM, 3 logical K-passes over [hi|lo] operands.
//   acc = Ahi*Whi + Ahi*Wlo + Alo*Whi
//   v   = acc + bias[n] + 2 * sum_r P[m,r]*U[r,n,t]   (+ReLU if mode==1)
// mode==1: emit bf16 [hi|lo] rows (stride 2N) for the next layer.
// mode==0: emit fp32 rows (stride N), no ReLU.
// ---------------------------------------------------------------------------
__global__ __launch_bounds__(256, 1)
void gemm_mma_kernel(const __nv_bfloat16* __restrict__ Ap,
                     const __nv_bfloat16* __restrict__ Bp,
                     const float* __restrict__ bias,
                     const float* __restrict__ P,
                     const float* __restrict__ U,
                     void* __restrict__ Cp,
                     int K, int N, int mode)
{
    extern __shared__ char smem[];
    const uint32_t sbase = smem_u32(smem);
    const int tid  = threadIdx.x;
    const int wid  = tid >> 5;
    const int lane = tid & 31;
    const int mBase = blockIdx.y * BM;
    const int nBase = blockIdx.x * BN;
    const int task  = mBase >> 10;
    const int ld    = 2 * K;                 // row stride of A' and B'
    const int KC    = K / BK;
    const int nChunks = 3 * KC;

    const int warp_m = (wid >> 2) * 64;   // 0 / 64
    const int warp_n = (wid & 3) * 32;    // 0 / 32 / 64 / 96

    // ---- per-thread producer addressing (4 A granules + 4 B granules) ------
    const __nv_bfloat16* gA[4];
    const __nv_bfloat16* gB[4];
    uint32_t sAB[4];
#pragma unroll
    for (int i = 0; i < 4; ++i) {
        int g = tid + (i << 8);           // 16B granule id 0..1023
        int r = g >> 3, q = g & 7;        // row 0..127, 16B col 0..7
        uint32_t off = (uint32_t)(r << 7) + (q << 4);
        sAB[i] = off ^ ((uint32_t)(r & 7) << 4);
        gA[i] = Ap + (size_t)(mBase + r) * ld + (q << 3);
        gB[i] = Bp + (size_t)(nBase + r) * ld + (q << 3);
    }

    // term mapping: chunk c -> (A offset, B offset) in elements
    auto chunk_off = [&](int c, int& aOff, int& bOff) {
        if (c < KC)            { aOff = c * BK;            bOff = c * BK; }
        else if (c < 2 * KC)   { aOff = (c - KC) * BK;     bOff = K + (c - KC) * BK; }
        else                   { aOff = K + (c - 2*KC)*BK; bOff = (c - 2 * KC) * BK; }
    };

    float acc[4][4][4];
#pragma unroll
    for (int mi = 0; mi < 4; ++mi)
#pragma unroll
        for (int ni = 0; ni < 4; ++ni)
#pragma unroll
            for (int j = 0; j < 4; ++j) acc[mi][ni][j] = 0.f;

    // ---- prologue: fill STAGES-1 stages -----------------------------------
#pragma unroll
    for (int c = 0; c < STAGES - 1; ++c) {
        const uint32_t stA = sbase + c * STAGE_BYTES;
        const uint32_t stB = stA + BM * 128;
        int aOff, bOff; chunk_off(c, aOff, bOff);
#pragma unroll
        for (int i = 0; i < 4; ++i) CP_ASYNC16(stA + sAB[i], gA[i] + aOff);
#pragma unroll
        for (int i = 0; i < 4; ++i) CP_ASYNC16(stB + sAB[i], gB[i] + bOff);
        CP_ASYNC_COMMIT();
    }

    // ---- ldmatrix addressing ----------------------------------------------
    uint32_t aRow[4], aXm[4], bRow[4], bXm[4];
    const uint32_t aCol = (uint32_t)(lane >> 4) << 4;
    const uint32_t bCol = (uint32_t)((lane >> 3) & 1) << 4;
#pragma unroll
    for (int mi = 0; mi < 4; ++mi) {
        int r = warp_m + mi * 16 + (lane & 15);
        aRow[mi] = (uint32_t)r << 7;
        aXm[mi]  = (uint32_t)(r & 7) << 4;
    }
#pragma unroll
    for (int ni = 0; ni < 4; ++ni) {
        int r = warp_n + ni * 8 + (lane & 7);
        bRow[ni] = (uint32_t)r << 7;
        bXm[ni]  = (uint32_t)(r & 7) << 4;
    }

    // ---- mainloop ----------------------------------------------------------
    for (int c = 0; c < nChunks; ++c) {
        CP_ASYNC_WAIT(STAGES - 2);
        __syncthreads();

        const int s = c & (STAGES - 1);
        const uint32_t stA = sbase + s * STAGE_BYTES;
        const uint32_t stB = stA + BM * 128;

#pragma unroll
        for (int kk = 0; kk < 4; ++kk) {
            const uint32_t kb = (uint32_t)kk << 5;   // +32 B per k16
            uint32_t a[4][4], b[4][2];
#pragma unroll
            for (int mi = 0; mi < 4; ++mi) {
                uint32_t addr = stA + aRow[mi] + ((kb + aCol) ^ aXm[mi]);
                LDMATRIX_X4(a[mi][0], a[mi][1], a[mi][2], a[mi][3], addr);
            }
#pragma unroll
            for (int ni = 0; ni < 4; ++ni) {
                uint32_t addr = stB + bRow[ni] + ((kb + bCol) ^ bXm[ni]);
                LDMATRIX_X2(b[ni][0], b[ni][1], addr);
            }
#pragma unroll
            for (int mi = 0; mi < 4; ++mi)
#pragma unroll
                for (int ni = 0; ni < 4; ++ni)
                    mma_bf16(acc[mi][ni], a[mi], b[ni]);
        }

        const int cn = c + STAGES - 1;
        if (cn < nChunks) {
            const int sn = cn & (STAGES - 1);
            const uint32_t nA = sbase + sn * STAGE_BYTES;
            const uint32_t nB = nA + BM * 128;
            int aOff, bOff; chunk_off(cn, aOff, bOff);
#pragma unroll
            for (int i = 0; i < 4; ++i) CP_ASYNC16(nA + sAB[i], gA[i] + aOff);
#pragma unroll
            for (int i = 0; i < 4; ++i) CP_ASYNC16(nB + sAB[i], gB[i] + bOff);
        }
        CP_ASYNC_COMMIT();
    }

    // ---- epilogue ----------------------------------------------------------
    CP_ASYNC_WAIT(0);
    __syncthreads();

    float* bias_s = reinterpret_cast<float*>(smem);               // [128]
    float* Us     = reinterpret_cast<float*>(smem + 1024);        // [8][128]
    float* Ps     = reinterpret_cast<float*>(smem + 1024 + 4096); // [128][8]

    if (tid < BN) bias_s[tid] = bias[nBase + tid];
#pragma unroll
    for (int i = 0; i < 4; ++i) {
        int idx = tid + (i << 8);
        int r = idx >> 7, n = idx & 127;
        Us[idx] = U[((size_t)r * N + nBase + n) * T_TASKS + task];
    }
    {
        int row = tid >> 1, half = (tid & 1) << 2;
        float4 v = *reinterpret_cast<const float4*>(
            P + (size_t)(mBase + row) * RNK + half);
        *reinterpret_cast<float4*>(&Ps[row * RNK + half]) = v;
    }
    __syncthreads();

#pragma unroll
    for (int mi = 0; mi < 4; ++mi) {
#pragma unroll
        for (int half = 0; half < 2; ++half) {
            const int rloc = warp_m + mi * 16 + (lane >> 2) + half * 8;
            const int gm   = mBase + rloc;
            float pr[RNK];
            {
                float4 p0 = *reinterpret_cast<const float4*>(&Ps[rloc * RNK]);
                float4 p1 = *reinterpret_cast<const float4*>(&Ps[rloc * RNK + 4]);
                pr[0]=p0.x; pr[1]=p0.y; pr[2]=p0.z; pr[3]=p0.w;
                pr[4]=p1.x; pr[5]=p1.y; pr[6]=p1.z; pr[7]=p1.w;
            }
#pragma unroll
            for (int ni = 0; ni < 4; ++ni) {
                const int nloc = warp_n + ni * 8 + ((lane & 3) << 1);
                float l0 = 0.f, l1 = 0.f;
#pragma unroll
                for (int q = 0; q < RNK; ++q) {
                    l0 += pr[q] * Us[(q << 7) + nloc];
                    l1 += pr[q] * Us[(q << 7) + nloc + 1];
                }
                float v0 = acc[mi][ni][half * 2 + 0] + bias_s[nloc]     + 2.f * l0;
                float v1 = acc[mi][ni][half * 2 + 1] + bias_s[nloc + 1] + 2.f * l1;
                if (mode == 1) {
                    v0 = fmaxf(v0, 0.f); v1 = fmaxf(v1, 0.f);
                    __nv_bfloat16 h0 = __float2bfloat16(v0);
                    __nv_bfloat16 h1 = __float2bfloat16(v1);
                    __nv_bfloat16 l0b = __float2bfloat16(v0 - __bfloat162float(h0));
                    __nv_bfloat16 l1b = __float2bfloat16(v1 - __bfloat162float(h1));
                    __nv_bfloat16* orow = (__nv_bfloat16*)Cp +
                        (size_t)gm * (2 * N) + nBase + nloc;
                    __nv_bfloat162 hp; hp.x = h0; hp.y = h1;
                    __nv_bfloat162 lp; lp.x = l0b; lp.y = l1b;
                    *reinterpret_cast<__nv_bfloat162*>(orow)     = hp;
                    *reinterpret_cast<__nv_bfloat162*>(orow + N) = lp;
                } else {
                    float* crow = (float*)Cp + (size_t)gm * N + nBase + nloc;
                    *reinterpret_cast<float2*>(crow) = make_float2(v0, v1);
                }
            }
        }
    }
}

// ---------------------------------------------------------------------------
// Host launcher
// ---------------------------------------------------------------------------
static void run_layer(const __nv_bfloat16* Ain, const float* W, const float* b,
                      const float* D, const float* U, void* Cout,
                      __nv_bfloat16* bS, float* p, int K, int N, int mode)
{
    convertW_kernel<<<dim3(N / 32, K / 32), 256>>>(W, bS, K, N);
    lora_down_kernel<<<M_ROWS / 8, 256>>>(Ain, D, p, K);
    cudaFuncSetAttribute(gemm_mma_kernel,
                         cudaFuncAttributeMaxDynamicSharedMemorySize, SMEM_BYTES);
    dim3 grid(N / BN, M_ROWS / BM);
    gemm_mma_kernel<<<grid, 256, SMEM_BYTES>>>(Ain, bS, b, p, U, Cout, K, N, mode);
}

extern "C" void kernel_launch(void* const* d_in, const int* in_sizes, int n_in,
                              void* d_out, int out_size)
{
    const float* x  = (const float*)d_in[0];
    const float* k0 = (const float*)d_in[1];
    const float* b0 = (const float*)d_in[2];
    const float* d0 = (const float*)d_in[3];
    const float* u0 = (const float*)d_in[4];
    const float* k1 = (const float*)d_in[5];
    const float* b1 = (const float*)d_in[6];
    const float* d1 = (const float*)d_in[7];
    const float* u1 = (const float*)d_in[8];
    const float* k2 = (const float*)d_in[9];
    const float* b2 = (const float*)d_in[10];
    const float* d2 = (const float*)d_in[11];
    const float* u2 = (const float*)d_in[12];
    float* out = (float*)d_out;

    __nv_bfloat16 *a0, *a1, *bS;
    float* p;
    cudaGetSymbolAddress((void**)&a0, g_A0);
    cudaGetSymbolAddress((void**)&a1, g_A1);
    cudaGetSymbolAddress((void**)&bS, g_B);
    cudaGetSymbolAddress((void**)&p,  g_p);

    // layer 0 input: x fp32 -> A0 [hi|lo]  (K = 1024)
    {
        size_t tot = (size_t)M_ROWS * 1024 / 4;
        convertA_kernel<<<(unsigned)((tot + 255) / 256), 256>>>(x, a0, 1024);
    }
    // layer 0: A0[.,1024] -> A1[.,2048] bf16, ReLU
    run_layer(a0, k0, b0, d0, u0, a1, bS, p, 1024, 2048, 1);
    // layer 1: A1[.,2048] -> A0[.,2048] bf16, ReLU   (x' no longer needed)
    run_layer(a1, k1, b1, d1, u1, a0, bS, p, 2048, 2048, 1);
    // layer 2: A0[.,2048] -> out fp32 [.,1024], no ReLU
    run_layer(a0, k2, b2, d2, u2, out, bS, p, 2048, 1024, 0);
}

// round 6
// speedup vs baseline: 4.1975x; 1.2791x over previous
#include <cuda_runtime.h>
#include <cuda_bf16.h>
#include <cstdint>

// ---------------------------------------------------------------------------
// LoRA multi-task MLP via mma.sync bf16 (plain sm_100 target).
// fp32 operands split hi/lo bf16 stored [hi|lo] (2K wide). GEMM does a SINGLE
// K-pass; per chunk it loads Ahi/Alo/Bhi/Blo and issues 3 MMA terms:
//   acc = Ahi*Bhi + Ahi*Blo + Alo*Bhi      (fp32 accumulate)
// Epilogue fuses bias + 2*P*U^t + ReLU + bf16[hi|lo] re-split AND the next
// layer's LoRA-down partials (per-warp partials staged in smem, summed per
// block -- race-free and deterministic -- then reduced by a tiny kernel).
// ---------------------------------------------------------------------------

#define T_TASKS 8
#define RNK 8
#define M_ROWS 8192

#define BM 128
#define BN 128
#define BK 64                         // true-K elements per chunk (128 B rows)
#define STAGES 3
#define TILE_BYTES (128 * 128)        // 16 KB per operand tile
#define STAGE_BYTES (4 * TILE_BYTES)  // Ahi|Alo|Bhi|Blo = 64 KB
#define SMEM_BYTES (STAGES * STAGE_BYTES)   // 192 KB

// ---- scratch (device globals; no allocation allowed) ----------------------
__device__ __nv_bfloat16 g_A0[(size_t)M_ROWS * 4096];   // [hi|lo], 64 MB
__device__ __nv_bfloat16 g_A1[(size_t)M_ROWS * 4096];   // [hi|lo], 64 MB
__device__ __nv_bfloat16 g_B [(size_t)2048   * 4096];   // [hi|lo], 16 MB
__device__ float g_p [M_ROWS * RNK];
__device__ float g_pp[16 * M_ROWS * RNK];               // per-n-block partials

// ---------------------------------------------------------------------------
__device__ __forceinline__ uint32_t smem_u32(const void* p) {
    uint32_t a;
    asm("{ .reg .u64 t; cvta.to.shared.u64 t, %1; cvt.u32.u64 %0, t; }"
        : "=r"(a) : "l"(p));
    return a;
}

#define CP_ASYNC16(smem, gptr) \
    asm volatile("cp.async.cg.shared.global [%0], [%1], 16;" \
                 :: "r"(smem), "l"(gptr) : "memory")
#define CP_ASYNC_COMMIT() asm volatile("cp.async.commit_group;" ::: "memory")
#define CP_ASYNC_WAIT(n)  asm volatile("cp.async.wait_group %0;" :: "n"(n) : "memory")

#define LDMATRIX_X4(r0,r1,r2,r3,addr) \
    asm volatile("ldmatrix.sync.aligned.m8n8.x4.shared.b16 {%0,%1,%2,%3}, [%4];" \
        : "=r"(r0),"=r"(r1),"=r"(r2),"=r"(r3) : "r"(addr))
#define LDMATRIX_X2(r0,r1,addr) \
    asm volatile("ldmatrix.sync.aligned.m8n8.x2.shared.b16 {%0,%1}, [%2];" \
        : "=r"(r0),"=r"(r1) : "r"(addr))

__device__ __forceinline__ void mma_bf16(float* c, const uint32_t* a,
                                         const uint32_t* b) {
    asm volatile(
        "mma.sync.aligned.m16n8k16.row.col.f32.bf16.bf16.f32 "
        "{%0,%1,%2,%3}, {%4,%5,%6,%7}, {%8,%9}, {%0,%1,%2,%3};"
        : "+f"(c[0]), "+f"(c[1]), "+f"(c[2]), "+f"(c[3])
        : "r"(a[0]), "r"(a[1]), "r"(a[2]), "r"(a[3]), "r"(b[0]), "r"(b[1]));
}

// ---------------------------------------------------------------------------
// Layer-0 LoRA down: P[m,r] = sum_k x[m,k]*D0[k,r,t], x fp32, K=1024.
// ---------------------------------------------------------------------------
__global__ __launch_bounds__(256)
void lora0_kernel(const float* __restrict__ x, const float* __restrict__ D,
                  float* __restrict__ P)
{
    __shared__ float Ds[RNK][1024];
    const int tid  = threadIdx.x;
    const int wid  = tid >> 5;
    const int lane = tid & 31;
    const int row  = blockIdx.x * 8 + wid;
    const int t    = (blockIdx.x * 8) >> 10;

    for (int idx = tid; idx < 1024 * RNK; idx += 256) {
        int k = idx >> 3, r = idx & 7;
        Ds[r][k] = D[(size_t)k * 64 + r * 8 + t];
    }
    __syncthreads();

    const float4* xr = reinterpret_cast<const float4*>(x + (size_t)row * 1024);
    float acc[RNK];
#pragma unroll
    for (int r = 0; r < RNK; ++r) acc[r] = 0.f;
#pragma unroll
    for (int i = 0; i < 8; ++i) {
        int kq = lane + 32 * i;
        float4 v = xr[kq];
        int k = kq << 2;
#pragma unroll
        for (int r = 0; r < RNK; ++r) {
            float4 d = *reinterpret_cast<const float4*>(&Ds[r][k]);
            acc[r] += v.x * d.x + v.y * d.y + v.z * d.z + v.w * d.w;
        }
    }
#pragma unroll
    for (int r = 0; r < RNK; ++r) {
        float v = acc[r];
#pragma unroll
        for (int o = 16; o > 0; o >>= 1) v += __shfl_down_sync(0xffffffffu, v, o);
        if (lane == 0) P[(size_t)row * RNK + r] = v;
    }
}

// ---------------------------------------------------------------------------
// P[m,r] = sum_nb Pp[nb][m][r]
// ---------------------------------------------------------------------------
__global__ __launch_bounds__(256)
void reduceP_kernel(const float* __restrict__ Pp, float* __restrict__ P, int nb)
{
    int i = blockIdx.x * 256 + threadIdx.x;      // over M_ROWS*RNK = 65536
    float s = 0.f;
    for (int b = 0; b < nb; ++b) s += Pp[(size_t)b * (M_ROWS * RNK) + i];
    P[i] = s;
}

// ---------------------------------------------------------------------------
// x[M,K] fp32 -> A'[M,2K] bf16 = [hi | lo]   (layer-0 input only)
// ---------------------------------------------------------------------------
__global__ __launch_bounds__(256)
void convertA_kernel(const float* __restrict__ A, __nv_bfloat16* __restrict__ Ap,
                     int K)
{
    size_t idx = (size_t)blockIdx.x * blockDim.x + threadIdx.x;
    size_t total = (size_t)M_ROWS * K / 4;
    if (idx >= total) return;
    int Kq = K >> 2;
    int m  = (int)(idx / Kq);
    int kq = (int)(idx - (size_t)m * Kq) << 2;
    float4 v = *reinterpret_cast<const float4*>(A + (size_t)m * K + kq);

    union { __nv_bfloat16 b[4]; uint2 u; } hp, lp;
    float vv[4] = {v.x, v.y, v.z, v.w};
#pragma unroll
    for (int i = 0; i < 4; ++i) {
        __nv_bfloat16 h = __float2bfloat16(vv[i]);
        hp.b[i] = h;
        lp.b[i] = __float2bfloat16(vv[i] - __bfloat162float(h));
    }
    size_t base = (size_t)m * 2 * K + kq;
    *reinterpret_cast<uint2*>(Ap + base)     = hp.u;
    *reinterpret_cast<uint2*>(Ap + base + K) = lp.u;
}

// ---------------------------------------------------------------------------
// W[K,N] fp32 -> B'[N,2K] bf16 = [hi^T | lo^T]
// ---------------------------------------------------------------------------
__global__ __launch_bounds__(256)
void convertW_kernel(const float* __restrict__ W, __nv_bfloat16* __restrict__ Bp,
                     int K, int N)
{
    __shared__ float t[32][33];
    int n0 = blockIdx.x * 32, k0 = blockIdx.y * 32;
    int tx = threadIdx.x & 31, ty = threadIdx.x >> 5;   // 32 x 8
#pragma unroll
    for (int i = 0; i < 4; ++i)
        t[ty + 8 * i][tx] = W[(size_t)(k0 + ty + 8 * i) * N + n0 + tx];
    __syncthreads();
#pragma unroll
    for (int i = 0; i < 4; ++i) {
        int nn = ty + 8 * i;
        float v = t[tx][nn];
        __nv_bfloat16 h = __float2bfloat16(v);
        __nv_bfloat16 l = __float2bfloat16(v - __bfloat162float(h));
        size_t rb = (size_t)(n0 + nn) * 2 * K + k0 + tx;
        Bp[rb]     = h;
        Bp[rb + K] = l;
    }
}

// ---------------------------------------------------------------------------
// Single-K-pass pipelined bf16 mma.sync GEMM (3 terms per chunk) with fused
// epilogue and race-free fused next-layer LoRA-down partials.
// mode==1: bf16 [hi|lo] output (stride 2N) + ReLU + fused P partials (Dn).
// mode==0: fp32 output (stride N), no ReLU, no P partials.
// ---------------------------------------------------------------------------
__global__ __launch_bounds__(256, 1)
void gemm_mma_kernel(const __nv_bfloat16* __restrict__ Ap,
                     const __nv_bfloat16* __restrict__ Bp,
                     const float* __restrict__ bias,
                     const float* __restrict__ P,
                     const float* __restrict__ U,
                     void* __restrict__ Cp,
                     const float* __restrict__ Dn,   // next-layer D or null
                     float* __restrict__ Pp,         // partial buffer or null
                     int K, int N, int mode)
{
    extern __shared__ char smem[];
    const uint32_t sbase = smem_u32(smem);
    const int tid  = threadIdx.x;
    const int wid  = tid >> 5;
    const int lane = tid & 31;
    const int mBase = blockIdx.y * BM;
    const int nBase = blockIdx.x * BN;
    const int task  = mBase >> 10;
    const int ld    = 2 * K;
    const int nChunks = K / BK;

    const int warp_m = (wid >> 2) * 64;   // 0 / 64
    const int warp_n = (wid & 3) * 32;    // 0 / 32 / 64 / 96

    // ---- producer addressing: 4 granules per tile per thread ---------------
    const __nv_bfloat16* gA[4];
    const __nv_bfloat16* gB[4];
    uint32_t sAB[4];
#pragma unroll
    for (int i = 0; i < 4; ++i) {
        int g = tid + (i << 8);           // 16B granule id 0..1023
        int r = g >> 3, q = g & 7;        // row 0..127, 16B col 0..7
        uint32_t off = (uint32_t)(r << 7) + (q << 4);
        sAB[i] = off ^ ((uint32_t)(r & 7) << 4);
        gA[i] = Ap + (size_t)(mBase + r) * ld + (q << 3);
        gB[i] = Bp + (size_t)(nBase + r) * ld + (q << 3);
    }

    float acc[4][4][4];
#pragma unroll
    for (int mi = 0; mi < 4; ++mi)
#pragma unroll
        for (int ni = 0; ni < 4; ++ni)
#pragma unroll
            for (int j = 0; j < 4; ++j) acc[mi][ni][j] = 0.f;

    // ---- prologue: fill STAGES-1 stages -----------------------------------
#pragma unroll
    for (int c = 0; c < STAGES - 1; ++c) {
        const uint32_t st = sbase + c * STAGE_BYTES;
        const int kc = c * BK;
#pragma unroll
        for (int i = 0; i < 4; ++i) {
            CP_ASYNC16(st + sAB[i],                  gA[i] + kc);      // Ahi
            CP_ASYNC16(st + TILE_BYTES   + sAB[i],   gA[i] + K + kc);  // Alo
            CP_ASYNC16(st + 2*TILE_BYTES + sAB[i],   gB[i] + kc);      // Bhi
            CP_ASYNC16(st + 3*TILE_BYTES + sAB[i],   gB[i] + K + kc);  // Blo
        }
        CP_ASYNC_COMMIT();
    }

    // ---- ldmatrix addressing ----------------------------------------------
    uint32_t aRow[4], aXm[4], bRow[4], bXm[4];
    const uint32_t aCol = (uint32_t)(lane >> 4) << 4;
    const uint32_t bCol = (uint32_t)((lane >> 3) & 1) << 4;
#pragma unroll
    for (int mi = 0; mi < 4; ++mi) {
        int r = warp_m + mi * 16 + (lane & 15);
        aRow[mi] = (uint32_t)r << 7;
        aXm[mi]  = (uint32_t)(r & 7) << 4;
    }
#pragma unroll
    for (int ni = 0; ni < 4; ++ni) {
        int r = warp_n + ni * 8 + (lane & 7);
        bRow[ni] = (uint32_t)r << 7;
        bXm[ni]  = (uint32_t)(r & 7) << 4;
    }

    // ---- mainloop ----------------------------------------------------------
    int s = 0;
    for (int c = 0; c < nChunks; ++c) {
        CP_ASYNC_WAIT(STAGES - 2);
        __syncthreads();

        const uint32_t stAhi = sbase + s * STAGE_BYTES;
        const uint32_t stAlo = stAhi + TILE_BYTES;
        const uint32_t stBhi = stAhi + 2 * TILE_BYTES;
        const uint32_t stBlo = stAhi + 3 * TILE_BYTES;

#pragma unroll
        for (int kk = 0; kk < 4; ++kk) {
            const uint32_t kb = (uint32_t)kk << 5;
            uint32_t ah[4][4], al[4][4], bh[4][2], bl[4][2];
#pragma unroll
            for (int mi = 0; mi < 4; ++mi) {
                uint32_t xo = (kb + aCol);
                LDMATRIX_X4(ah[mi][0], ah[mi][1], ah[mi][2], ah[mi][3],
                            stAhi + aRow[mi] + (xo ^ aXm[mi]));
                LDMATRIX_X4(al[mi][0], al[mi][1], al[mi][2], al[mi][3],
                            stAlo + aRow[mi] + (xo ^ aXm[mi]));
            }
#pragma unroll
            for (int ni = 0; ni < 4; ++ni) {
                uint32_t xo = (kb + bCol);
                LDMATRIX_X2(bh[ni][0], bh[ni][1],
                            stBhi + bRow[ni] + (xo ^ bXm[ni]));
                LDMATRIX_X2(bl[ni][0], bl[ni][1],
                            stBlo + bRow[ni] + (xo ^ bXm[ni]));
            }
#pragma unroll
            for (int mi = 0; mi < 4; ++mi)
#pragma unroll
                for (int ni = 0; ni < 4; ++ni) {
                    mma_bf16(acc[mi][ni], ah[mi], bh[ni]);
                    mma_bf16(acc[mi][ni], ah[mi], bl[ni]);
                    mma_bf16(acc[mi][ni], al[mi], bh[ni]);
                }
        }

        const int cn = c + STAGES - 1;
        if (cn < nChunks) {
            int sn = s + (STAGES - 1); if (sn >= STAGES) sn -= STAGES;
            const uint32_t st = sbase + sn * STAGE_BYTES;
            const int kc = cn * BK;
#pragma unroll
            for (int i = 0; i < 4; ++i) {
                CP_ASYNC16(st + sAB[i],                gA[i] + kc);
                CP_ASYNC16(st + TILE_BYTES   + sAB[i], gA[i] + K + kc);
                CP_ASYNC16(st + 2*TILE_BYTES + sAB[i], gB[i] + kc);
                CP_ASYNC16(st + 3*TILE_BYTES + sAB[i], gB[i] + K + kc);
            }
        }
        CP_ASYNC_COMMIT();
        if (++s == STAGES) s = 0;
    }

    // ---- epilogue ----------------------------------------------------------
    CP_ASYNC_WAIT(0);
    __syncthreads();

    float* bias_s = reinterpret_cast<float*>(smem);                // [128]
    float* Us     = reinterpret_cast<float*>(smem + 1024);         // [8][128]
    float* Ps     = reinterpret_cast<float*>(smem + 1024 + 4096);  // [128][8]
    float* Dsn    = reinterpret_cast<float*>(smem + 1024 + 8192);  // [128][8]
    float* sPP    = reinterpret_cast<float*>(smem + 16384);        // [4][128][8]

    if (tid < BN) bias_s[tid] = bias[nBase + tid];
#pragma unroll
    for (int i = 0; i < 4; ++i) {
        int idx = tid + (i << 8);
        int r = idx >> 7, n = idx & 127;
        Us[idx] = U[((size_t)r * N + nBase + n) * T_TASKS + task];
    }
    {
        int row = tid >> 1, half = (tid & 1) << 2;
        float4 v = *reinterpret_cast<const float4*>(
            P + (size_t)(mBase + row) * RNK + half);
        *reinterpret_cast<float4*>(&Ps[row * RNK + half]) = v;
    }
    if (mode == 1) {
#pragma unroll
        for (int i = 0; i < 4; ++i) {
            int idx = tid + (i << 8);
            int n = idx >> 3, r = idx & 7;
            Dsn[idx] = Dn[(size_t)(nBase + n) * 64 + r * 8 + task];
        }
    }
    __syncthreads();

#pragma unroll
    for (int mi = 0; mi < 4; ++mi) {
#pragma unroll
        for (int half = 0; half < 2; ++half) {
            const int rloc = warp_m + mi * 16 + (lane >> 2) + half * 8;
            const int gm   = mBase + rloc;
            float pr[RNK];
            {
                float4 p0 = *reinterpret_cast<const float4*>(&Ps[rloc * RNK]);
                float4 p1 = *reinterpret_cast<const float4*>(&Ps[rloc * RNK + 4]);
                pr[0]=p0.x; pr[1]=p0.y; pr[2]=p0.z; pr[3]=p0.w;
                pr[4]=p1.x; pr[5]=p1.y; pr[6]=p1.z; pr[7]=p1.w;
            }
            float pp[RNK];
#pragma unroll
            for (int r = 0; r < RNK; ++r) pp[r] = 0.f;

#pragma unroll
            for (int ni = 0; ni < 4; ++ni) {
                const int nloc = warp_n + ni * 8 + ((lane & 3) << 1);
                float l0 = 0.f, l1 = 0.f;
#pragma unroll
                for (int q = 0; q < RNK; ++q) {
                    l0 += pr[q] * Us[(q << 7) + nloc];
                    l1 += pr[q] * Us[(q << 7) + nloc + 1];
                }
                float v0 = acc[mi][ni][half * 2 + 0] + bias_s[nloc]     + 2.f * l0;
                float v1 = acc[mi][ni][half * 2 + 1] + bias_s[nloc + 1] + 2.f * l1;
                if (mode == 1) {
                    v0 = fmaxf(v0, 0.f); v1 = fmaxf(v1, 0.f);
                    __nv_bfloat16 h0 = __float2bfloat16(v0);
                    __nv_bfloat16 h1 = __float2bfloat16(v1);
                    __nv_bfloat16 lo0 = __float2bfloat16(v0 - __bfloat162float(h0));
                    __nv_bfloat16 lo1 = __float2bfloat16(v1 - __bfloat162float(h1));
                    __nv_bfloat16* orow = (__nv_bfloat16*)Cp +
                        (size_t)gm * (2 * N) + nBase + nloc;
                    __nv_bfloat162 hv; hv.x = h0; hv.y = h1;
                    __nv_bfloat162 lv; lv.x = lo0; lv.y = lo1;
                    *reinterpret_cast<__nv_bfloat162*>(orow)     = hv;
                    *reinterpret_cast<__nv_bfloat162*>(orow + N) = lv;
#pragma unroll
                    for (int r = 0; r < RNK; ++r)
                        pp[r] += v0 * Dsn[(nloc << 3) + r]
                               + v1 * Dsn[((nloc + 1) << 3) + r];
                } else {
                    float* crow = (float*)Cp + (size_t)gm * N + nBase + nloc;
                    *reinterpret_cast<float2*>(crow) = make_float2(v0, v1);
                }
            }

            if (mode == 1) {
                // reduce across the quad (4 lanes share rloc)
#pragma unroll
                for (int r = 0; r < RNK; ++r) {
                    pp[r] += __shfl_xor_sync(0xffffffffu, pp[r], 1);
                    pp[r] += __shfl_xor_sync(0xffffffffu, pp[r], 2);
                }
                // per-warp slot: warps sharing warp_m write disjoint rows per slot
                if ((lane & 3) == 0) {
                    float* dst = &sPP[(((wid & 3) << 7) + rloc) * RNK];
#pragma unroll
                    for (int r = 0; r < RNK; ++r) dst[r] = pp[r];
                }
            }
        }
    }

    if (mode == 1) {
        __syncthreads();
        // sum the 4 warp-n slots -> one deterministic partial per block
        for (int i = tid; i < BM * RNK; i += 256) {
            float sum = sPP[i] + sPP[1024 + i] + sPP[2048 + i] + sPP[3072 + i];
            Pp[(size_t)blockIdx.x * (M_ROWS * RNK) + (size_t)mBase * RNK + i] = sum;
        }
    }
}

// ---------------------------------------------------------------------------
// Host launcher
// ---------------------------------------------------------------------------
extern "C" void kernel_launch(void* const* d_in, const int* in_sizes, int n_in,
                              void* d_out, int out_size)
{
    const float* x  = (const float*)d_in[0];
    const float* k0 = (const float*)d_in[1];
    const float* b0 = (const float*)d_in[2];
    const float* d0 = (const float*)d_in[3];
    const float* u0 = (const float*)d_in[4];
    const float* k1 = (const float*)d_in[5];
    const float* b1 = (const float*)d_in[6];
    const float* d1 = (const float*)d_in[7];
    const float* u1 = (const float*)d_in[8];
    const float* k2 = (const float*)d_in[9];
    const float* b2 = (const float*)d_in[10];
    const float* d2 = (const float*)d_in[11];
    const float* u2 = (const float*)d_in[12];
    float* out = (float*)d_out;

    __nv_bfloat16 *a0, *a1, *bS;
    float *p, *pp;
    cudaGetSymbolAddress((void**)&a0, g_A0);
    cudaGetSymbolAddress((void**)&a1, g_A1);
    cudaGetSymbolAddress((void**)&bS, g_B);
    cudaGetSymbolAddress((void**)&p,  g_p);
    cudaGetSymbolAddress((void**)&pp, g_pp);

    cudaFuncSetAttribute(gemm_mma_kernel,
                         cudaFuncAttributeMaxDynamicSharedMemorySize, SMEM_BYTES);

    // layer-0 prep: x -> A0 [hi|lo]; P0 from fp32 x directly
    {
        size_t tot = (size_t)M_ROWS * 1024 / 4;
        convertA_kernel<<<(unsigned)((tot + 255) / 256), 256>>>(x, a0, 1024);
    }
    lora0_kernel<<<M_ROWS / 8, 256>>>(x, d0, p);

    // layer 0: A0[.,1024] -> A1[.,2048] bf16+ReLU, fused P' partials (d1)
    convertW_kernel<<<dim3(2048 / 32, 1024 / 32), 256>>>(k0, bS, 1024, 2048);
    gemm_mma_kernel<<<dim3(2048 / BN, M_ROWS / BM), 256, SMEM_BYTES>>>(
        a0, bS, b0, p, u0, a1, d1, pp, 1024, 2048, 1);
    reduceP_kernel<<<(M_ROWS * RNK) / 256, 256>>>(pp, p, 2048 / BN);

    // layer 1: A1[.,2048] -> A0[.,2048] bf16+ReLU, fused P' partials (d2)
    convertW_kernel<<<dim3(2048 / 32, 2048 / 32), 256>>>(k1, bS, 2048, 2048);
    gemm_mma_kernel<<<dim3(2048 / BN, M_ROWS / BM), 256, SMEM_BYTES>>>(
        a1, bS, b1, p, u1, a0, d2, pp, 2048, 2048, 1);
    reduceP_kernel<<<(M_ROWS * RNK) / 256, 256>>>(pp, p, 2048 / BN);

    // layer 2: A0[.,2048] -> out fp32 [.,1024], no ReLU
    convertW_kernel<<<dim3(1024 / 32, 2048 / 32), 256>>>(k2, bS, 2048, 1024);
    gemm_mma_kernel<<<dim3(1024 / BN, M_ROWS / BM), 256, SMEM_BYTES>>>(
        a0, bS, b2, p, u2, out, nullptr, nullptr, 2048, 1024, 0);
}